// round 10
// baseline (speedup 1.0000x reference)
#include <cuda_runtime.h>
#include <math_constants.h>
#include <cstdint>

#define N_BINS     15
#define TILE_ROWS  64
#define ROW_BYTES  512                            // 128 fp32
#define TILE_BYTES (TILE_ROWS * ROW_BYTES)        // 32768
#define LAB_BYTES  (TILE_ROWS * 4)                // 256
#define STAGES     3
#define NTHREADS   256

// dynamic smem layout
#define SMEM_FULL   0                              // STAGES x 8B mbarriers
#define SMEM_EMPTY  64                             // STAGES x 8B mbarriers
#define SMEM_LAB    128                            // STAGES x 256B labels
#define SMEM_DATA   1024                           // STAGES x 32KB logits
#define SMEM_TOTAL  (SMEM_DATA + STAGES * TILE_BYTES)   // 99328

// Global scratch (no allocation allowed). Zeroed at module load; the fused
// finalizer re-zeroes after each use, so every graph replay starts clean.
__device__ float    g_cnt[N_BINS];
__device__ float    g_conf[N_BINS];
__device__ float    g_acc[N_BINS];
__device__ unsigned g_done;

#define LOG2E 1.4426950408889634f

__device__ __forceinline__ float ex2f(float x) {
    float r;
    asm volatile("ex2.approx.f32 %0, %1;" : "=f"(r) : "f"(x));
    return r;
}

__device__ __forceinline__ void mbar_init(uint32_t a, uint32_t cnt) {
    asm volatile("mbarrier.init.shared.b64 [%0], %1;" :: "r"(a), "r"(cnt) : "memory");
}
__device__ __forceinline__ void mbar_arrive(uint32_t a) {
    asm volatile("mbarrier.arrive.shared.b64 _, [%0];" :: "r"(a) : "memory");
}
__device__ __forceinline__ void mbar_wait(uint32_t a, uint32_t ph) {
    asm volatile(
        "{\n\t.reg .pred P;\n"
        "W%=:\n\t"
        "mbarrier.try_wait.parity.acquire.cta.shared::cta.b64 P, [%0], %1, 0x989680;\n\t"
        "@P bra D%=;\n\t"
        "bra W%=;\n"
        "D%=:\n\t}"
        :: "r"(a), "r"(ph) : "memory");
}
__device__ __forceinline__ void issue_tile(uint32_t full, uint32_t d_data,
                                           uint32_t d_lab, const char* gdata,
                                           const char* glab) {
    asm volatile("mbarrier.arrive.expect_tx.shared.b64 _, [%0], %1;"
                 :: "r"(full), "r"((uint32_t)(TILE_BYTES + LAB_BYTES)) : "memory");
    asm volatile("cp.async.bulk.shared::cta.global.mbarrier::complete_tx::bytes "
                 "[%0], [%1], %2, [%3];"
                 :: "r"(d_data), "l"(gdata), "r"((uint32_t)TILE_BYTES), "r"(full)
                 : "memory");
    asm volatile("cp.async.bulk.shared::cta.global.mbarrier::complete_tx::bytes "
                 "[%0], [%1], %2, [%3];"
                 :: "r"(d_lab), "l"(glab), "r"((uint32_t)LAB_BYTES), "r"(full)
                 : "memory");
}

// TMA-fed pipeline: 64-row tiles through a 3-stage SMEM ring. 8 warps per CTA,
// 8 rows per warp per tile (8-lane segments, 2 rows per lane, full-line reads
// from SMEM). Register histogram (lane b owns bin b); fused finalize.
__global__ void __launch_bounds__(NTHREADS) mce_main_kernel(
    const float* __restrict__ logits,
    const int*   __restrict__ labels,
    float*       __restrict__ out,
    int nrows)
{
    extern __shared__ char smem[];
    uint32_t sb = (uint32_t)__cvta_generic_to_shared(smem);

    __shared__ float s_cnt[N_BINS];
    __shared__ float s_conf[N_BINS];
    __shared__ float s_acc[N_BINS];
    __shared__ bool  s_last;

    int tid  = threadIdx.x;
    int lane = tid & 31;
    int wid  = tid >> 5;                   // warp 0..7
    int seg  = lane >> 3;                  // segment 0..3
    int sub  = lane & 7;                   // lane within 8-lane segment

    int ntiles = nrows / TILE_ROWS;
    int nmy    = (ntiles > (int)blockIdx.x)
               ? (ntiles - 1 - (int)blockIdx.x) / (int)gridDim.x + 1 : 0;

    if (tid < N_BINS) { s_cnt[tid] = 0.f; s_conf[tid] = 0.f; s_acc[tid] = 0.f; }
    if (tid == 0) {
        #pragma unroll
        for (int s = 0; s < STAGES; s++) {
            mbar_init(sb + SMEM_FULL  + 8 * s, 1);
            mbar_init(sb + SMEM_EMPTY + 8 * s, NTHREADS);
        }
        asm volatile("fence.proxy.async.shared::cta;" ::: "memory");
        int k = nmy < STAGES ? nmy : STAGES;
        for (int i = 0; i < k; i++) {
            int t = blockIdx.x + i * gridDim.x;
            issue_tile(sb + SMEM_FULL + 8 * i,
                       sb + SMEM_DATA + i * TILE_BYTES,
                       sb + SMEM_LAB  + i * LAB_BYTES,
                       (const char*)logits + (size_t)t * TILE_BYTES,
                       (const char*)labels + (size_t)t * LAB_BYTES);
        }
    }
    __syncthreads();

    float r_cnt = 0.0f, r_conf = 0.0f, r_acc = 0.0f;

    int stage = 0, ph = 0;
    int lc = 0;
    for (int t = blockIdx.x; t < ntiles; t += gridDim.x, lc++) {
        mbar_wait(sb + SMEM_FULL + 8 * stage, (uint32_t)ph);

        const char* dptr = smem + SMEM_DATA + stage * TILE_BYTES;
        const int*  lptr = (const int*)(smem + SMEM_LAB + stage * LAB_BYTES);

        int rowLA = wid * 8 + seg;         // local rows: 8 per warp
        int rowLB = rowLA + 4;

        // full-line SMEM reads: 4 LDS.128 per row per lane (stride 128B)
        float4 vA[4], vB[4];
        const float4* rA = (const float4*)(dptr + rowLA * ROW_BYTES) + sub;
        const float4* rB = (const float4*)(dptr + rowLB * ROW_BYTES) + sub;
        #pragma unroll
        for (int i = 0; i < 4; i++) vA[i] = rA[8 * i];
        #pragma unroll
        for (int i = 0; i < 4; i++) vB[i] = rB[8 * i];

        int labA = lptr[rowLA];
        int labB = lptr[rowLB];
        float lvA = *(const float*)(dptr + rowLA * ROW_BYTES + labA * 4);
        float lvB = *(const float*)(dptr + rowLB * ROW_BYTES + labB * 4);

        // ---- per-lane max over 16 values each row ----
        float p0 = fmaxf(fmaxf(vA[0].x, vA[0].y), fmaxf(vA[0].z, vA[0].w));
        float p1 = fmaxf(fmaxf(vA[1].x, vA[1].y), fmaxf(vA[1].z, vA[1].w));
        float p2 = fmaxf(fmaxf(vA[2].x, vA[2].y), fmaxf(vA[2].z, vA[2].w));
        float p3 = fmaxf(fmaxf(vA[3].x, vA[3].y), fmaxf(vA[3].z, vA[3].w));
        float mA = fmaxf(fmaxf(p0, p1), fmaxf(p2, p3));
        float q0 = fmaxf(fmaxf(vB[0].x, vB[0].y), fmaxf(vB[0].z, vB[0].w));
        float q1 = fmaxf(fmaxf(vB[1].x, vB[1].y), fmaxf(vB[1].z, vB[1].w));
        float q2 = fmaxf(fmaxf(vB[2].x, vB[2].y), fmaxf(vB[2].z, vB[2].w));
        float q3 = fmaxf(fmaxf(vB[3].x, vB[3].y), fmaxf(vB[3].z, vB[3].w));
        float mB = fmaxf(fmaxf(q0, q1), fmaxf(q2, q3));
        #pragma unroll
        for (int off = 1; off <= 4; off <<= 1) {
            mA = fmaxf(mA, __shfl_xor_sync(0xffffffffu, mA, off));
            mB = fmaxf(mB, __shfl_xor_sync(0xffffffffu, mB, off));
        }

        // ---- sum of exp(x-m) via ex2(x*log2e - m*log2e) ----
        float mLA = mA * LOG2E, mLB = mB * LOG2E;
        float sA = 0.0f, sB = 0.0f;
        #pragma unroll
        for (int i = 0; i < 4; i++) {
            sA += (ex2f(fmaf(vA[i].x, LOG2E, -mLA)) + ex2f(fmaf(vA[i].y, LOG2E, -mLA)))
                + (ex2f(fmaf(vA[i].z, LOG2E, -mLA)) + ex2f(fmaf(vA[i].w, LOG2E, -mLA)));
            sB += (ex2f(fmaf(vB[i].x, LOG2E, -mLB)) + ex2f(fmaf(vB[i].y, LOG2E, -mLB)))
                + (ex2f(fmaf(vB[i].z, LOG2E, -mLB)) + ex2f(fmaf(vB[i].w, LOG2E, -mLB)));
        }
        #pragma unroll
        for (int off = 1; off <= 4; off <<= 1) {
            sA += __shfl_xor_sync(0xffffffffu, sA, off);
            sB += __shfl_xor_sync(0xffffffffu, sB, off);
        }

        float confA = __fdividef(1.0f, sA);
        float confB = __fdividef(1.0f, sB);
        unsigned bA = __ballot_sync(0xffffffffu, lvA == mA);
        unsigned bB = __ballot_sync(0xffffffffu, lvB == mB);

        #pragma unroll
        for (int r = 0; r < 8; r++) {
            float cf = (r < 4)
                     ? __shfl_sync(0xffffffffu, confA, (r & 3) * 8)
                     : __shfl_sync(0xffffffffu, confB, (r & 3) * 8);
            unsigned sh = (unsigned)(r & 3) * 8;
            unsigned ab = (r < 4) ? ((bA >> sh) & 0xffu) : ((bB >> sh) & 0xffu);
            int bin = min(__float2int_ru(cf * (float)N_BINS) - 1, N_BINS - 1);
            if (bin == lane) {
                r_cnt  += 1.0f;
                r_conf += cf;
                r_acc  += (ab != 0u) ? 1.0f : 0.0f;
            }
        }

        // release stage, reissue 3 tiles ahead
        asm volatile("fence.proxy.async.shared::cta;" ::: "memory");
        mbar_arrive(sb + SMEM_EMPTY + 8 * stage);
        if (tid == 0 && lc + STAGES < nmy) {
            mbar_wait(sb + SMEM_EMPTY + 8 * stage, (uint32_t)ph);
            int tn = t + STAGES * gridDim.x;
            issue_tile(sb + SMEM_FULL + 8 * stage,
                       sb + SMEM_DATA + stage * TILE_BYTES,
                       sb + SMEM_LAB  + stage * LAB_BYTES,
                       (const char*)logits + (size_t)tn * TILE_BYTES,
                       (const char*)labels + (size_t)tn * LAB_BYTES);
        }
        if (++stage == STAGES) { stage = 0; ph ^= 1; }
    }

    // ---- remainder rows (nrows % 64): block 0, one warp per row, gmem ----
    int rem_base = ntiles * TILE_ROWS;
    if (blockIdx.x == 0 && rem_base < nrows) {
        for (int row = rem_base + wid; row < nrows; row += 8) {
            float4 v = ((const float4*)logits)[(size_t)row * 32 + lane];
            float m = fmaxf(fmaxf(v.x, v.y), fmaxf(v.z, v.w));
            #pragma unroll
            for (int off = 16; off; off >>= 1)
                m = fmaxf(m, __shfl_xor_sync(0xffffffffu, m, off));
            float mL = m * LOG2E;
            float s = (ex2f(fmaf(v.x, LOG2E, -mL)) + ex2f(fmaf(v.y, LOG2E, -mL)))
                    + (ex2f(fmaf(v.z, LOG2E, -mL)) + ex2f(fmaf(v.w, LOG2E, -mL)));
            #pragma unroll
            for (int off = 16; off; off >>= 1)
                s += __shfl_xor_sync(0xffffffffu, s, off);
            int l = labels[row];
            bool mine = ((l >> 2) == lane);
            int  c = l & 3;
            float lv = (c == 0) ? v.x : (c == 1) ? v.y : (c == 2) ? v.z : v.w;
            unsigned b = __ballot_sync(0xffffffffu, mine && (lv == m));
            float cf = __fdividef(1.0f, s);
            int bin = min(__float2int_ru(cf * (float)N_BINS) - 1, N_BINS - 1);
            if (bin == lane) {
                r_cnt  += 1.0f;
                r_conf += cf;
                r_acc  += (b != 0u) ? 1.0f : 0.0f;
            }
        }
    }

    // ---- flush: registers -> shared -> global (once per block) ----
    __syncthreads();
    if (lane < N_BINS && r_cnt != 0.0f) {
        atomicAdd(&s_cnt[lane],  r_cnt);
        atomicAdd(&s_conf[lane], r_conf);
        atomicAdd(&s_acc[lane],  r_acc);
    }
    __syncthreads();
    if (tid < N_BINS) {
        float c = s_cnt[tid];
        if (c != 0.0f) {
            atomicAdd(&g_cnt[tid],  c);
            atomicAdd(&g_conf[tid], s_conf[tid]);
            atomicAdd(&g_acc[tid],  s_acc[tid]);
        }
    }
    __threadfence();
    __syncthreads();

    // ---- last block finalizes (fused; no second launch) ----
    if (tid == 0)
        s_last = (atomicAdd(&g_done, 1u) == gridDim.x - 1u);
    __syncthreads();
    if (s_last && tid == 0) {
        volatile float* vc = g_cnt;
        volatile float* vp = g_conf;
        volatile float* va = g_acc;
        float mce = -CUDART_INF_F;
        #pragma unroll
        for (int i = 0; i < N_BINS; i++) {
            float c    = vc[i];
            float prob = 0.0f, accu = 0.0f;
            if (c > 0.0f) {
                prob = vp[i] / c;
                accu = va[i] / c;
                float gap = fabsf(prob - accu);
                if (gap > mce) mce = gap;
            }
            out[1 + i]          = prob;
            out[1 + N_BINS + i] = accu;
            vc[i] = 0.0f; vp[i] = 0.0f; va[i] = 0.0f;
        }
        out[0] = mce;
        g_done = 0u;
    }
}

extern "C" void kernel_launch(void* const* d_in, const int* in_sizes, int n_in,
                              void* d_out, int out_size) {
    const float* logits = (const float*)d_in[0];
    const int*   labels = (const int*)d_in[1];
    int nrows = in_sizes[1];               // labels element count == N rows

    cudaFuncSetAttribute(mce_main_kernel,
                         cudaFuncAttributeMaxDynamicSharedMemorySize, SMEM_TOTAL);
    // 2 CTAs/SM (99KB smem each) x 148 SMs = 296 blocks
    mce_main_kernel<<<296, NTHREADS, SMEM_TOTAL>>>(logits, labels,
                                                   (float*)d_out, nrows);
}

// round 11
// speedup vs baseline: 1.0225x; 1.0225x over previous
#include <cuda_runtime.h>
#include <math_constants.h>

#define N_BINS 15
#define RPW 8          // rows per warp per iter (2 rows per lane, 4 segments)

// Global scratch (no allocation allowed). Zeroed at module load; the fused
// finalizer re-zeroes after each use, so every graph replay starts from zero.
__device__ float    g_cnt[N_BINS];
__device__ float    g_conf[N_BINS];
__device__ float    g_acc[N_BINS];
__device__ unsigned g_done;

__device__ __forceinline__ float ex2f(float x) {
    float r;
    asm volatile("ex2.approx.f32 %0, %1;" : "=f"(r) : "f"(x));
    return r;
}

#define LOG2E 1.4426950408889634f

// Extract column `lab` (0..127) of the row held by this 8-lane segment.
// Lane sub owns float4 indices {sub, sub+8, sub+16, sub+24}; returns the
// value on the owning lane (garbage elsewhere) plus an ownership flag.
// Pure SEL chain — no dependent memory load.
__device__ __forceinline__ float extract_col(const float4 v[4], int lab, int sub,
                                             bool& owner)
{
    int f4  = lab >> 2;            // float4 index 0..31
    owner   = ((f4 & 7) == sub);   // owning lane within segment
    int i   = f4 >> 3;             // which of my 4 float4s
    int c   = lab & 3;             // component
    float4 f01 = (i & 1) ? v[1] : v[0];
    float4 f23 = (i & 1) ? v[3] : v[2];
    float4 f   = (i & 2) ? f23 : f01;
    float  lo  = (c & 1) ? f.y : f.x;
    float  hi  = (c & 1) ? f.w : f.z;
    return (c & 2) ? hi : lo;
}

// 8 lanes per row, 2 rows per lane: each LDG.128 covers 4 FULL 128B lines.
// A warp processes 8 consecutive rows per iteration (4 KB, front-batched).
// No atomics and no dependent loads in the hot loop. Register histogram:
// lane b (<15) owns bin b.
__global__ void __launch_bounds__(256, 4) mce_main_kernel(
    const float4* __restrict__ logits4,   // [nrows * 32] float4
    const int*    __restrict__ labels,    // [nrows]
    float*        __restrict__ out,
    int nrows)
{
    __shared__ float s_cnt[N_BINS];
    __shared__ float s_conf[N_BINS];
    __shared__ float s_acc[N_BINS];
    __shared__ bool  s_last;

    int tid = threadIdx.x;
    if (tid < N_BINS) {
        s_cnt[tid]  = 0.0f;
        s_conf[tid] = 0.0f;
        s_acc[tid]  = 0.0f;
    }
    __syncthreads();

    int lane   = tid & 31;
    int seg    = lane >> 3;                // segment 0..3
    int sub    = lane & 7;                 // lane within 8-lane segment
    int warp   = (blockIdx.x * blockDim.x + tid) >> 5;
    int nwarps = (gridDim.x * blockDim.x) >> 5;

    float r_cnt = 0.0f, r_conf = 0.0f, r_acc = 0.0f;

    for (int base = warp * RPW; base < nrows; base += nwarps * RPW) {
        int rowA = base + seg;             // rows 0..3 of the group
        int rowB = base + seg + 4;         // rows 4..7 of the group
        int rowAc = (rowA < nrows) ? rowA : (nrows - 1);
        int rowBc = (rowB < nrows) ? rowB : (nrows - 1);

        // ---- independent front batch: 8 full-line LDG.128 + 2 label LDGs ----
        float4 vA[4], vB[4];
        const float4* rpA = logits4 + (size_t)rowAc * 32 + sub;
        const float4* rpB = logits4 + (size_t)rowBc * 32 + sub;
        #pragma unroll
        for (int i = 0; i < 4; i++) vA[i] = __ldcs(rpA + 8 * i);
        #pragma unroll
        for (int i = 0; i < 4; i++) vB[i] = __ldcs(rpB + 8 * i);
        int labA = labels[rowAc];
        int labB = labels[rowBc];

        // ---- per-lane max over 16 values each row ----
        float p0 = fmaxf(fmaxf(vA[0].x, vA[0].y), fmaxf(vA[0].z, vA[0].w));
        float p1 = fmaxf(fmaxf(vA[1].x, vA[1].y), fmaxf(vA[1].z, vA[1].w));
        float p2 = fmaxf(fmaxf(vA[2].x, vA[2].y), fmaxf(vA[2].z, vA[2].w));
        float p3 = fmaxf(fmaxf(vA[3].x, vA[3].y), fmaxf(vA[3].z, vA[3].w));
        float mA = fmaxf(fmaxf(p0, p1), fmaxf(p2, p3));
        float q0 = fmaxf(fmaxf(vB[0].x, vB[0].y), fmaxf(vB[0].z, vB[0].w));
        float q1 = fmaxf(fmaxf(vB[1].x, vB[1].y), fmaxf(vB[1].z, vB[1].w));
        float q2 = fmaxf(fmaxf(vB[2].x, vB[2].y), fmaxf(vB[2].z, vB[2].w));
        float q3 = fmaxf(fmaxf(vB[3].x, vB[3].y), fmaxf(vB[3].z, vB[3].w));
        float mB = fmaxf(fmaxf(q0, q1), fmaxf(q2, q3));

        // 3-level segment butterflies, two rows interleaved
        #pragma unroll
        for (int off = 1; off <= 4; off <<= 1) {
            mA = fmaxf(mA, __shfl_xor_sync(0xffffffffu, mA, off));
            mB = fmaxf(mB, __shfl_xor_sync(0xffffffffu, mB, off));
        }

        // ---- sum of exp(x - m) = ex2(x*log2e - m*log2e) ----
        float mLA = mA * LOG2E, mLB = mB * LOG2E;
        float sA = 0.0f, sB = 0.0f;
        #pragma unroll
        for (int i = 0; i < 4; i++) {
            float a0 = ex2f(fmaf(vA[i].x, LOG2E, -mLA));
            float a1 = ex2f(fmaf(vA[i].y, LOG2E, -mLA));
            float a2 = ex2f(fmaf(vA[i].z, LOG2E, -mLA));
            float a3 = ex2f(fmaf(vA[i].w, LOG2E, -mLA));
            sA += (a0 + a1) + (a2 + a3);
            float b0 = ex2f(fmaf(vB[i].x, LOG2E, -mLB));
            float b1 = ex2f(fmaf(vB[i].y, LOG2E, -mLB));
            float b2 = ex2f(fmaf(vB[i].z, LOG2E, -mLB));
            float b3 = ex2f(fmaf(vB[i].w, LOG2E, -mLB));
            sB += (b0 + b1) + (b2 + b3);
        }
        #pragma unroll
        for (int off = 1; off <= 4; off <<= 1) {
            sA += __shfl_xor_sync(0xffffffffu, sA, off);
            sB += __shfl_xor_sync(0xffffffffu, sB, off);
        }

        float confA = __fdividef(1.0f, sA);    // = exp(max)/sum exp
        float confB = __fdividef(1.0f, sB);

        // ---- accuracy: label column extracted from registers (no load) ----
        bool ownA, ownB;
        float lvA = extract_col(vA, labA, sub, ownA);
        float lvB = extract_col(vB, labB, sub, ownB);
        unsigned bA = __ballot_sync(0xffffffffu, ownA && (lvA == mA));
        unsigned bB = __ballot_sync(0xffffffffu, ownB && (lvB == mB));

        int nr = min(RPW, nrows - base);
        #pragma unroll
        for (int r = 0; r < RPW; r++) {
            float cf = (r < 4)
                     ? __shfl_sync(0xffffffffu, confA, (r & 3) * 8)
                     : __shfl_sync(0xffffffffu, confB, (r & 3) * 8);
            unsigned sh   = (unsigned)(r & 3) * 8;
            unsigned abit = (r < 4) ? ((bA >> sh) & 0xffu)
                                    : ((bB >> sh) & 0xffu);
            // bin i covers (i/15, (i+1)/15]; conf >= 1/128 -> bin >= 0
            int bin = min(__float2int_ru(cf * (float)N_BINS) - 1, N_BINS - 1);
            if (bin == lane && r < nr) {
                r_cnt  += 1.0f;
                r_conf += cf;
                r_acc  += (abit != 0u) ? 1.0f : 0.0f;
            }
        }
    }

    // ---- flush: registers -> shared -> global (once per block) ----
    if (lane < N_BINS && r_cnt != 0.0f) {
        atomicAdd(&s_cnt[lane],  r_cnt);
        atomicAdd(&s_conf[lane], r_conf);
        atomicAdd(&s_acc[lane],  r_acc);
    }
    __syncthreads();
    if (tid < N_BINS) {
        float c = s_cnt[tid];
        if (c != 0.0f) {
            atomicAdd(&g_cnt[tid],  c);
            atomicAdd(&g_conf[tid], s_conf[tid]);
            atomicAdd(&g_acc[tid],  s_acc[tid]);
        }
    }
    __threadfence();
    __syncthreads();

    // ---- last block finalizes (fused; no second launch) ----
    if (tid == 0)
        s_last = (atomicAdd(&g_done, 1u) == gridDim.x - 1u);
    __syncthreads();
    if (s_last && tid == 0) {
        volatile float* vc = g_cnt;
        volatile float* vp = g_conf;
        volatile float* va = g_acc;
        float mce = -CUDART_INF_F;
        #pragma unroll
        for (int i = 0; i < N_BINS; i++) {
            float c    = vc[i];
            float prob = 0.0f, accu = 0.0f;
            if (c > 0.0f) {
                prob = vp[i] / c;
                accu = va[i] / c;
                float gap = fabsf(prob - accu);
                if (gap > mce) mce = gap;
            }
            out[1 + i]          = prob;
            out[1 + N_BINS + i] = accu;
            vc[i] = 0.0f; vp[i] = 0.0f; va[i] = 0.0f;   // reset for next replay
        }
        out[0] = mce;
        g_done = 0u;
    }
}

extern "C" void kernel_launch(void* const* d_in, const int* in_sizes, int n_in,
                              void* d_out, int out_size) {
    const float4* logits4 = (const float4*)d_in[0];
    const int*    labels  = (const int*)d_in[1];
    int nrows = in_sizes[1];               // labels element count == N rows

    // 3 CTAs/SM x 148 SMs = 444 blocks (best measured occupancy point)
    mce_main_kernel<<<444, 256>>>(logits4, labels, (float*)d_out, nrows);
}

// round 12
// speedup vs baseline: 1.0452x; 1.0222x over previous
#include <cuda_runtime.h>
#include <math_constants.h>

#define N_BINS 15
#define RPW 8          // rows per warp per iter (one row per 4-lane segment)

// Global scratch (no allocation allowed). Zeroed at module load; the fused
// finalizer re-zeroes after each use, so every graph replay starts from zero.
__device__ float    g_cnt[N_BINS];
__device__ float    g_conf[N_BINS];
__device__ float    g_acc[N_BINS];
__device__ unsigned g_done;

__device__ __forceinline__ float ex2f(float x) {
    float r;
    asm volatile("ex2.approx.f32 %0, %1;" : "=f"(r) : "f"(x));
    return r;
}

#define LOG2E 1.4426950408889634f

// Extract column `lab` (0..127) of the row held by this 4-lane segment.
// Lane sub owns float4 indices {sub, sub+4, ..., sub+28} (stride 4).
// Returns the value on the owning lane (garbage elsewhere) + ownership flag.
// Pure SEL chain — replaces R5's chained labels->logits load.
__device__ __forceinline__ float extract_col4(const float4 v[RPW], int lab,
                                              int sub, bool& owner)
{
    int f4 = lab >> 2;                 // float4 index 0..31
    owner  = ((f4 & 3) == sub);        // owning lane within 4-lane segment
    int i  = f4 >> 2;                  // which of my 8 float4s (0..7)
    int c  = lab & 3;                  // component
    // component-extract each candidate (3 SELs each), then 8->1 mux by i
    float e[RPW];
    #pragma unroll
    for (int k = 0; k < RPW; k++) {
        float lo = (c & 1) ? v[k].y : v[k].x;
        float hi = (c & 1) ? v[k].w : v[k].z;
        e[k] = (c & 2) ? hi : lo;
    }
    float a01 = (i & 1) ? e[1] : e[0];
    float a23 = (i & 1) ? e[3] : e[2];
    float a45 = (i & 1) ? e[5] : e[4];
    float a67 = (i & 1) ? e[7] : e[6];
    float b0  = (i & 2) ? a23 : a01;
    float b1  = (i & 2) ? a67 : a45;
    return (i & 4) ? b1 : b0;
}

// R5 layout: 4 lanes per row, lane covers 32 floats (8 float4, stride-4).
// A warp processes 8 consecutive rows per iteration (4 KB, front-batched).
// No atomics and no dependent loads in the hot loop. Register histogram:
// lane b (<15) owns bin b.
__global__ void __launch_bounds__(256, 4) mce_main_kernel(
    const float4* __restrict__ logits4,   // [nrows * 32] float4
    const int*    __restrict__ labels,    // [nrows]
    float*        __restrict__ out,
    int nrows)
{
    __shared__ float s_cnt[N_BINS];
    __shared__ float s_conf[N_BINS];
    __shared__ float s_acc[N_BINS];
    __shared__ bool  s_last;

    int tid = threadIdx.x;
    if (tid < N_BINS) {
        s_cnt[tid]  = 0.0f;
        s_conf[tid] = 0.0f;
        s_acc[tid]  = 0.0f;
    }
    __syncthreads();

    int lane   = tid & 31;
    int seg    = lane >> 2;                // row within group (0..7)
    int sub    = lane & 3;                 // lane within 4-lane segment
    int warp   = (blockIdx.x * blockDim.x + tid) >> 5;
    int nwarps = (gridDim.x * blockDim.x) >> 5;

    float r_cnt = 0.0f, r_conf = 0.0f, r_acc = 0.0f;

    for (int base = warp * RPW; base < nrows; base += nwarps * RPW) {
        int row  = base + seg;
        int rowc = (row < nrows) ? row : (nrows - 1);   // clamp tail

        // ---- independent front batch: 8 LDG.128 + 1 label LDG per lane ----
        int lab = labels[rowc];            // broadcast within segment
        float4 v[RPW];
        const float4* rp = logits4 + (size_t)rowc * 32 + sub;
        #pragma unroll
        for (int i = 0; i < RPW; i++) v[i] = __ldcs(rp + 4 * i);

        // ---- per-lane max over 32 values, tree ----
        float pm[RPW];
        #pragma unroll
        for (int i = 0; i < RPW; i++)
            pm[i] = fmaxf(fmaxf(v[i].x, v[i].y), fmaxf(v[i].z, v[i].w));
        float m = fmaxf(fmaxf(fmaxf(pm[0], pm[1]), fmaxf(pm[2], pm[3])),
                        fmaxf(fmaxf(pm[4], pm[5]), fmaxf(pm[6], pm[7])));
        // segment butterfly: 2 levels, all 8 rows reduced per instruction
        m = fmaxf(m, __shfl_xor_sync(0xffffffffu, m, 1));
        m = fmaxf(m, __shfl_xor_sync(0xffffffffu, m, 2));

        // ---- sum of exp(x - m) = ex2(x*log2e - m*log2e) ----
        float mL = m * LOG2E;
        float ps[RPW];
        #pragma unroll
        for (int i = 0; i < RPW; i++) {
            float e0 = ex2f(fmaf(v[i].x, LOG2E, -mL));
            float e1 = ex2f(fmaf(v[i].y, LOG2E, -mL));
            float e2 = ex2f(fmaf(v[i].z, LOG2E, -mL));
            float e3 = ex2f(fmaf(v[i].w, LOG2E, -mL));
            ps[i] = (e0 + e1) + (e2 + e3);
        }
        float s = ((ps[0] + ps[1]) + (ps[2] + ps[3]))
                + ((ps[4] + ps[5]) + (ps[6] + ps[7]));
        s += __shfl_xor_sync(0xffffffffu, s, 1);
        s += __shfl_xor_sync(0xffffffffu, s, 2);

        float conf = __fdividef(1.0f, s);      // = exp(max)/sum exp

        // ---- accuracy: label column extracted from registers (no load) ----
        bool own;
        float lv = extract_col4(v, lab, sub, own);
        unsigned b = __ballot_sync(0xffffffffu, own && (lv == m));

        int nr = min(RPW, nrows - base);
        #pragma unroll
        for (int r = 0; r < RPW; r++) {
            float cf = __shfl_sync(0xffffffffu, conf, r * 4);
            unsigned abit = (b >> (4 * r)) & 0xfu;
            // bin i covers (i/15, (i+1)/15]; conf >= 1/128 -> bin >= 0
            int bin = min(__float2int_ru(cf * (float)N_BINS) - 1, N_BINS - 1);
            if (bin == lane && r < nr) {
                r_cnt  += 1.0f;
                r_conf += cf;
                r_acc  += (abit != 0u) ? 1.0f : 0.0f;
            }
        }
    }

    // ---- flush: registers -> shared -> global (once per block) ----
    if (lane < N_BINS && r_cnt != 0.0f) {
        atomicAdd(&s_cnt[lane],  r_cnt);
        atomicAdd(&s_conf[lane], r_conf);
        atomicAdd(&s_acc[lane],  r_acc);
    }
    __syncthreads();
    if (tid < N_BINS) {
        float c = s_cnt[tid];
        if (c != 0.0f) {
            atomicAdd(&g_cnt[tid],  c);
            atomicAdd(&g_conf[tid], s_conf[tid]);
            atomicAdd(&g_acc[tid],  s_acc[tid]);
        }
    }
    __threadfence();
    __syncthreads();

    // ---- last block finalizes (fused; no second launch) ----
    if (tid == 0)
        s_last = (atomicAdd(&g_done, 1u) == gridDim.x - 1u);
    __syncthreads();
    if (s_last && tid == 0) {
        volatile float* vc = g_cnt;
        volatile float* vp = g_conf;
        volatile float* va = g_acc;
        float mce = -CUDART_INF_F;
        #pragma unroll
        for (int i = 0; i < N_BINS; i++) {
            float c    = vc[i];
            float prob = 0.0f, accu = 0.0f;
            if (c > 0.0f) {
                prob = vp[i] / c;
                accu = va[i] / c;
                float gap = fabsf(prob - accu);
                if (gap > mce) mce = gap;
            }
            out[1 + i]          = prob;
            out[1 + N_BINS + i] = accu;
            vc[i] = 0.0f; vp[i] = 0.0f; va[i] = 0.0f;   // reset for next replay
        }
        out[0] = mce;
        g_done = 0u;
    }
}

extern "C" void kernel_launch(void* const* d_in, const int* in_sizes, int n_in,
                              void* d_out, int out_size) {
    const float4* logits4 = (const float4*)d_in[0];
    const int*    labels  = (const int*)d_in[1];
    int nrows = in_sizes[1];               // labels element count == N rows

    // 3 CTAs/SM x 148 SMs = 444 blocks (R5's proven best occupancy point)
    mce_main_kernel<<<444, 256>>>(logits4, labels, (float*)d_out, nrows);
}

// round 13
// speedup vs baseline: 1.0534x; 1.0078x over previous
#include <cuda_runtime.h>
#include <math_constants.h>

#define N_BINS 15
#define RPW 8          // rows per warp per iter (one row per 4-lane segment)

// Global scratch (no allocation allowed). Zeroed at module load; the fused
// finalizer re-zeroes after each use, so every graph replay starts from zero.
__device__ float    g_cnt[N_BINS];
__device__ float    g_conf[N_BINS];
__device__ float    g_acc[N_BINS];
__device__ unsigned g_done;

__device__ __forceinline__ float ex2f(float x) {
    float r;
    asm volatile("ex2.approx.f32 %0, %1;" : "=f"(r) : "f"(x));
    return r;
}

#define LOG2E 1.4426950408889634f

// Extract column `lab` (0..127) of the row held by this 4-lane segment.
// Lane sub owns float4 indices {sub, sub+4, ..., sub+28} (stride 4).
// Returns the value on the owning lane (garbage elsewhere) + ownership flag.
// Pure SEL chain — replaces R5's chained labels->logits load.
__device__ __forceinline__ float extract_col4(const float4 v[RPW], int lab,
                                              int sub, bool& owner)
{
    int f4 = lab >> 2;                 // float4 index 0..31
    owner  = ((f4 & 3) == sub);        // owning lane within 4-lane segment
    int i  = f4 >> 2;                  // which of my 8 float4s (0..7)
    int c  = lab & 3;                  // component
    // component-extract each candidate (3 SELs each), then 8->1 mux by i
    float e[RPW];
    #pragma unroll
    for (int k = 0; k < RPW; k++) {
        float lo = (c & 1) ? v[k].y : v[k].x;
        float hi = (c & 1) ? v[k].w : v[k].z;
        e[k] = (c & 2) ? hi : lo;
    }
    float a01 = (i & 1) ? e[1] : e[0];
    float a23 = (i & 1) ? e[3] : e[2];
    float a45 = (i & 1) ? e[5] : e[4];
    float a67 = (i & 1) ? e[7] : e[6];
    float b0  = (i & 2) ? a23 : a01;
    float b1  = (i & 2) ? a67 : a45;
    return (i & 4) ? b1 : b0;
}

// R5 layout: 4 lanes per row, lane covers 32 floats (8 float4, stride-4).
// A warp processes 8 consecutive rows per iteration (4 KB, front-batched).
// No atomics and no dependent loads in the hot loop. Register histogram:
// lane b (<15) owns bin b.
__global__ void __launch_bounds__(256, 4) mce_main_kernel(
    const float4* __restrict__ logits4,   // [nrows * 32] float4
    const int*    __restrict__ labels,    // [nrows]
    float*        __restrict__ out,
    int nrows)
{
    __shared__ float s_cnt[N_BINS];
    __shared__ float s_conf[N_BINS];
    __shared__ float s_acc[N_BINS];
    __shared__ bool  s_last;

    int tid = threadIdx.x;
    if (tid < N_BINS) {
        s_cnt[tid]  = 0.0f;
        s_conf[tid] = 0.0f;
        s_acc[tid]  = 0.0f;
    }
    __syncthreads();

    int lane   = tid & 31;
    int seg    = lane >> 2;                // row within group (0..7)
    int sub    = lane & 3;                 // lane within 4-lane segment
    int warp   = (blockIdx.x * blockDim.x + tid) >> 5;
    int nwarps = (gridDim.x * blockDim.x) >> 5;

    float r_cnt = 0.0f, r_conf = 0.0f, r_acc = 0.0f;

    for (int base = warp * RPW; base < nrows; base += nwarps * RPW) {
        int row  = base + seg;
        int rowc = (row < nrows) ? row : (nrows - 1);   // clamp tail

        // ---- independent front batch: 8 LDG.128 + 1 label LDG per lane ----
        int lab = labels[rowc];            // broadcast within segment
        float4 v[RPW];
        const float4* rp = logits4 + (size_t)rowc * 32 + sub;
        #pragma unroll
        for (int i = 0; i < RPW; i++) v[i] = __ldcs(rp + 4 * i);

        // ---- per-lane max over 32 values, tree ----
        float pm[RPW];
        #pragma unroll
        for (int i = 0; i < RPW; i++)
            pm[i] = fmaxf(fmaxf(v[i].x, v[i].y), fmaxf(v[i].z, v[i].w));
        float m = fmaxf(fmaxf(fmaxf(pm[0], pm[1]), fmaxf(pm[2], pm[3])),
                        fmaxf(fmaxf(pm[4], pm[5]), fmaxf(pm[6], pm[7])));
        // segment butterfly: 2 levels, all 8 rows reduced per instruction
        m = fmaxf(m, __shfl_xor_sync(0xffffffffu, m, 1));
        m = fmaxf(m, __shfl_xor_sync(0xffffffffu, m, 2));

        // ---- sum of exp(x - m) = ex2(x*log2e - m*log2e) ----
        float mL = m * LOG2E;
        float ps[RPW];
        #pragma unroll
        for (int i = 0; i < RPW; i++) {
            float e0 = ex2f(fmaf(v[i].x, LOG2E, -mL));
            float e1 = ex2f(fmaf(v[i].y, LOG2E, -mL));
            float e2 = ex2f(fmaf(v[i].z, LOG2E, -mL));
            float e3 = ex2f(fmaf(v[i].w, LOG2E, -mL));
            ps[i] = (e0 + e1) + (e2 + e3);
        }
        float s = ((ps[0] + ps[1]) + (ps[2] + ps[3]))
                + ((ps[4] + ps[5]) + (ps[6] + ps[7]));
        s += __shfl_xor_sync(0xffffffffu, s, 1);
        s += __shfl_xor_sync(0xffffffffu, s, 2);

        float conf = __fdividef(1.0f, s);      // = exp(max)/sum exp

        // ---- accuracy: label column extracted from registers (no load) ----
        bool own;
        float lv = extract_col4(v, lab, sub, own);
        unsigned b = __ballot_sync(0xffffffffu, own && (lv == m));

        int nr = min(RPW, nrows - base);
        #pragma unroll
        for (int r = 0; r < RPW; r++) {
            float cf = __shfl_sync(0xffffffffu, conf, r * 4);
            unsigned abit = (b >> (4 * r)) & 0xfu;
            // bin i covers (i/15, (i+1)/15]; conf >= 1/128 -> bin >= 0
            int bin = min(__float2int_ru(cf * (float)N_BINS) - 1, N_BINS - 1);
            if (bin == lane && r < nr) {
                r_cnt  += 1.0f;
                r_conf += cf;
                r_acc  += (abit != 0u) ? 1.0f : 0.0f;
            }
        }
    }

    // ---- flush: registers -> shared -> global (once per block) ----
    if (lane < N_BINS && r_cnt != 0.0f) {
        atomicAdd(&s_cnt[lane],  r_cnt);
        atomicAdd(&s_conf[lane], r_conf);
        atomicAdd(&s_acc[lane],  r_acc);
    }
    __syncthreads();
    if (tid < N_BINS) {
        float c = s_cnt[tid];
        if (c != 0.0f) {
            atomicAdd(&g_cnt[tid],  c);
            atomicAdd(&g_conf[tid], s_conf[tid]);
            atomicAdd(&g_acc[tid],  s_acc[tid]);
        }
    }
    __threadfence();
    __syncthreads();

    // ---- last block finalizes (fused; no second launch) ----
    if (tid == 0)
        s_last = (atomicAdd(&g_done, 1u) == gridDim.x - 1u);
    __syncthreads();
    if (s_last && tid == 0) {
        volatile float* vc = g_cnt;
        volatile float* vp = g_conf;
        volatile float* va = g_acc;
        float mce = -CUDART_INF_F;
        #pragma unroll
        for (int i = 0; i < N_BINS; i++) {
            float c    = vc[i];
            float prob = 0.0f, accu = 0.0f;
            if (c > 0.0f) {
                prob = vp[i] / c;
                accu = va[i] / c;
                float gap = fabsf(prob - accu);
                if (gap > mce) mce = gap;
            }
            out[1 + i]          = prob;
            out[1 + N_BINS + i] = accu;
            vc[i] = 0.0f; vp[i] = 0.0f; va[i] = 0.0f;   // reset for next replay
        }
        out[0] = mce;
        g_done = 0u;
    }
}

extern "C" void kernel_launch(void* const* d_in, const int* in_sizes, int n_in,
                              void* d_out, int out_size) {
    const float4* logits4 = (const float4*)d_in[0];
    const int*    labels  = (const int*)d_in[1];
    int nrows = in_sizes[1];               // labels element count == N rows

    // 3 CTAs/SM x 148 SMs = 444 blocks (R5's proven best occupancy point)
    mce_main_kernel<<<444, 256>>>(logits4, labels, (float*)d_out, nrows);
}